// round 14
// baseline (speedup 1.0000x reference)
#include <cuda_runtime.h>
#include <cstdint>

#define B  32
#define D  768
#define H  3072
#define T  8
#define MH 192

typedef unsigned long long ull;

// ---------------- scratch (device globals) ----------------------------------
__device__ float g_m  [B*D];
__device__ float g_f0 [B*D];
__device__ float g_Ap [B*T*D];
__device__ float g_z  [B*H];
__device__ float g_f  [B*H];
__device__ float g_Z1 [B*T*H];
__device__ float g_base[B*D];
__device__ float g_F2 [B*T*D];
__device__ float g_coef[B*T*6];
__device__ float g_df0[B*D];
__device__ float g_dzp[B*H];
__device__ float g_df [B*H];

// ---------------- packed f32x2 helpers --------------------------------------
__device__ __forceinline__ void ffma2(ull &d, ull a, ull b) {
    asm("fma.rn.f32x2 %0, %1, %2, %0;" : "+l"(d) : "l"(a), "l"(b));
}
__device__ __forceinline__ ull bcast2(float w) {
    ull r; asm("mov.b64 %0, {%1, %1};" : "=l"(r) : "f"(w)); return r;
}
__device__ __forceinline__ void unpack2(ull v, float &lo, float &hi) {
    asm("mov.b64 {%0, %1}, %2;" : "=f"(lo), "=f"(hi) : "l"(v));
}
__device__ __forceinline__ ull addp(ull a, ull b) {
    ull r; asm("add.rn.f32x2 %0, %1, %2;" : "=l"(r) : "l"(a), "l"(b)); return r;
}
__device__ __forceinline__ void red4(float* p, float4 f) {
    asm volatile("red.global.add.v4.f32 [%0], {%1,%2,%3,%4};"
                 :: "l"(p), "f"(f.x), "f"(f.y), "f"(f.z), "f"(f.w) : "memory");
}
// ---------------- mbarrier helpers -------------------------------------------
__device__ __forceinline__ void mbar_init(unsigned mbar, unsigned cnt) {
    asm volatile("mbarrier.init.shared.b64 [%0], %1;" :: "r"(mbar), "r"(cnt) : "memory");
}
__device__ __forceinline__ void mbar_wait(unsigned mbar, unsigned parity) {
    asm volatile(
        "{\n\t.reg .pred P;\n"
        "W_%=:\n\t"
        "mbarrier.try_wait.parity.acquire.cta.shared::cta.b64 P, [%0], %1;\n\t"
        "@P bra D_%=;\n\t"
        "bra W_%=;\n"
        "D_%=:\n\t}"
        :: "r"(mbar), "r"(parity) : "memory");
}
__device__ __forceinline__ void mbar_arrive(unsigned mbar) {
    asm volatile("mbarrier.arrive.release.cta.shared::cta.b64 _, [%0];"
                 :: "r"(mbar) : "memory");
}
template<int NC>
__device__ __forceinline__ void issue_tile(const float* wrow0, int t,
                                           unsigned swb, unsigned fullb) {
    asm volatile("mbarrier.arrive.expect_tx.shared.b64 _, [%0], %1;"
                 :: "r"(fullb), "r"(8192u) : "memory");
    const float* src = wrow0 + (size_t)t * 8 * NC;
    unsigned dst = swb + (unsigned)(t % 5) * 8192u;
    #pragma unroll
    for (int r = 0; r < 8; r++) {
        asm volatile(
            "cp.async.bulk.shared::cta.global.mbarrier::complete_tx::bytes "
            "[%0], [%1], 1024, [%2];"
            :: "r"(dst + r * 1024u), "l"(src + (size_t)r * NC), "r"(fullb)
            : "memory");
    }
}

// ---------------- K1: patch mean ---------------------------------------------
__global__ void patch_mean_kernel(const float* __restrict__ x) {
    int bc = blockIdx.x;            // 0..95
    int b = bc / 3, c = bc % 3;
    int tid = threadIdx.x;          // 256
    int dy = tid >> 4, dx = tid & 15;
    const float* base = x + (((size_t)b * 3 + c) * 224 + dy) * 224 + dx;
    float s = 0.f;
    #pragma unroll
    for (int py = 0; py < 14; py++) {
        const float* r = base + py * 16 * 224;
        #pragma unroll
        for (int px = 0; px < 14; px++) s += r[px * 16];
    }
    g_m[b * D + c * 256 + dy * 16 + dx] = s * (1.0f / 196.0f);
}

// ---------------- init: bias preload + zeros ---------------------------------
__global__ void init_kernel(const float* __restrict__ bp,
                            const float* __restrict__ b1,
                            const float* __restrict__ b2) {
    int i = blockIdx.x * 256 + threadIdx.x;
    if (i < B * D) { g_f0[i] = bp[i % D]; g_base[i] = b2[i % D]; }
    if (i < B * H) g_z[i] = b1[i % H];
    for (int j = i; j < B * T * D; j += gridDim.x * 256) { g_Ap[j] = 0.f; g_F2[j] = 0.f; }
    for (int j = i; j < B * T * H; j += gridDim.x * 256) g_Z1[j] = 0.f;
}

__global__ void relu_kernel() {
    int i = blockIdx.x * 256 + threadIdx.x;
    if (i < B * H) g_f[i] = fmaxf(g_z[i], 0.f);
}
__global__ void mask_kernel() {
    int i = blockIdx.x * 256 + threadIdx.x;
    if (i < B * H) g_df[i] = (g_z[i] > 0.f) ? g_dzp[i] : 0.f;
}

// ---------------- skinny GEMM v8: free-running warp pipeline ------------------
// Tile 256 cols x 32 rows; warps = 2ct x 2rh x 2kh; lane = 4 cols x 8 row-pairs
// packed over rows. NO __syncthreads in main loop: W via 5-stage bulk-DMA with
// full/empty mbarriers (warps drift up to 4 tiles); A warp-private smem.
// MODE: 0:g_f0/g_Ap  1:g_z/g_Z1  2:g_base/g_F2  3:g_dzp(A=g_df0)  4:dst(A=g_df)
template<int KTOT, int NC, int MODE>
__global__ void __launch_bounds__(256, 2) gemm8(
    const float* __restrict__ W0,
    const float* __restrict__ Wd,
    float* __restrict__ dst)
{
    __shared__ __align__(128) float sW[5 * 2048];   // 40KB: 5 stages of 8k x 256
    __shared__ __align__(16)  float sA[8 * 128];    // 4KB: per-warp 8k x 16
    __shared__ __align__(8)   ull   smb[10];        // full[5], empty[5]

    const int tid  = threadIdx.x;
    const int w    = tid >> 5;
    const int lane = tid & 31;
    const int ct   = w & 1;
    const int rh   = (w >> 1) & 1;
    const int kh   = w >> 2;

    const unsigned swb  = (unsigned)__cvta_generic_to_shared(sW);
    const unsigned mbf  = (unsigned)__cvta_generic_to_shared(smb);      // full
    const unsigned mbe  = mbf + 40;                                     // empty

    const float* A;
    if      (MODE == 0) A = g_m;
    else if (MODE == 1) A = g_f0;
    else if (MODE == 2) A = g_f;
    else if (MODE == 3) A = g_df0;
    else                A = g_df;

    const int n0 = blockIdx.x * 256;
    const int gt = n0 / NC;
    const int c0 = n0 % NC;
    const float* wbase = (gt == 0 ? W0 : Wd + (size_t)(gt - 1) * KTOT * NC) + c0;

    const int KC    = KTOT / gridDim.y;
    const int kbeg  = blockIdx.y * KC;
    const int tiles = KC >> 3;
    const float* wrow0 = wbase + (size_t)kbeg * NC;

    if (tid == 0) {
        #pragma unroll
        for (int i = 0; i < 5; i++) { mbar_init(mbf + i * 8, 1); mbar_init(mbe + i * 8, 8); }
        asm volatile("fence.proxy.async.shared::cta;" ::: "memory");
    }
    __syncthreads();

    if (tid == 0) {
        #pragma unroll
        for (int tp = 0; tp < 4; tp++)
            if (tp < tiles) issue_tile<NC>(wrow0, tp, swb, mbf + (tp % 5) * 8);
    }

    ull acc[32];
    #pragma unroll
    for (int i = 0; i < 32; i++) acc[i] = 0ULL;

    // per-warp A: rows rh*16+(lane&15), k quad (lane>>4)*4
    const int r16 = lane & 15, kq = (lane >> 4) * 4;
    const float* aptr = A + (size_t)(rh * 16 + r16) * KTOT + kbeg + kq;
    float* sAw = sA + w * 128;
    float4 av = *(const float4*)aptr;

    for (int t = 0; t < tiles; t++) {
        float4 avn;
        if (t + 1 < tiles) avn = *(const float4*)(aptr + (t + 1) * 8);
        __syncwarp();
        sAw[(kq + 0) * 16 + r16] = av.x;
        sAw[(kq + 1) * 16 + r16] = av.y;
        sAw[(kq + 2) * 16 + r16] = av.z;
        sAw[(kq + 3) * 16 + r16] = av.w;
        __syncwarp();

        mbar_wait(mbf + (t % 5) * 8, (unsigned)((t / 5) & 1));

        const float* sWk = &sW[(t % 5) * 2048 + ct * 128 + 4 * lane];
        #pragma unroll
        for (int kk = 0; kk < 4; kk++) {
            const int k = 2 * kk + kh;
            float4 wv = *(const float4*)(sWk + k * 256);
            const ulonglong2* ap = (const ulonglong2*)(sAw + k * 16);
            ulonglong2 a0 = ap[0], a1 = ap[1], a2 = ap[2], a3 = ap[3];
            ull wb0 = bcast2(wv.x), wb1 = bcast2(wv.y);
            ull wb2 = bcast2(wv.z), wb3 = bcast2(wv.w);
            ffma2(acc[0],  a0.x, wb0); ffma2(acc[1],  a0.x, wb1);
            ffma2(acc[2],  a0.x, wb2); ffma2(acc[3],  a0.x, wb3);
            ffma2(acc[4],  a0.y, wb0); ffma2(acc[5],  a0.y, wb1);
            ffma2(acc[6],  a0.y, wb2); ffma2(acc[7],  a0.y, wb3);
            ffma2(acc[8],  a1.x, wb0); ffma2(acc[9],  a1.x, wb1);
            ffma2(acc[10], a1.x, wb2); ffma2(acc[11], a1.x, wb3);
            ffma2(acc[12], a1.y, wb0); ffma2(acc[13], a1.y, wb1);
            ffma2(acc[14], a1.y, wb2); ffma2(acc[15], a1.y, wb3);
            ffma2(acc[16], a2.x, wb0); ffma2(acc[17], a2.x, wb1);
            ffma2(acc[18], a2.x, wb2); ffma2(acc[19], a2.x, wb3);
            ffma2(acc[20], a2.y, wb0); ffma2(acc[21], a2.y, wb1);
            ffma2(acc[22], a2.y, wb2); ffma2(acc[23], a2.y, wb3);
            ffma2(acc[24], a3.x, wb0); ffma2(acc[25], a3.x, wb1);
            ffma2(acc[26], a3.x, wb2); ffma2(acc[27], a3.x, wb3);
            ffma2(acc[28], a3.y, wb0); ffma2(acc[29], a3.y, wb1);
            ffma2(acc[30], a3.y, wb2); ffma2(acc[31], a3.y, wb3);
        }

        if (lane == 0) mbar_arrive(mbe + (t % 5) * 8);

        if (tid == 0 && t + 4 < tiles) {
            const int tp = t + 4;
            mbar_wait(mbe + (tp % 5) * 8, (unsigned)(((tp / 5) & 1) ^ 1));
            issue_tile<NC>(wrow0, tp, swb, mbf + (tp % 5) * 8);
        }
        av = avn;
    }

    // ---- merge kh pair via one smem round, flush once ----
    __syncthreads();
    ull* sred = (ull*)sW;
    const int role = w & 3;               // (ct, rh)
    if (kh == 1) {
        #pragma unroll
        for (int i = 0; i < 32; i++) sred[role * 1024 + i * 32 + lane] = acc[i];
    }
    __syncthreads();
    if (kh == 0) {
        #pragma unroll
        for (int i = 0; i < 32; i++)
            acc[i] = addp(acc[i], sred[role * 1024 + i * 32 + lane]);

        const int cg = c0 + ct * 128 + 4 * lane;
        #pragma unroll
        for (int p = 0; p < 8; p++) {
            const int row = rh * 16 + 2 * p;
            float4 vlo, vhi;
            unpack2(acc[p * 4 + 0], vlo.x, vhi.x);
            unpack2(acc[p * 4 + 1], vlo.y, vhi.y);
            unpack2(acc[p * 4 + 2], vlo.z, vhi.z);
            unpack2(acc[p * 4 + 3], vlo.w, vhi.w);
            #pragma unroll
            for (int h = 0; h < 2; h++) {
                const int r = row + h;
                float4 f = h ? vhi : vlo;
                float* p_;
                if constexpr (MODE == 0)
                    p_ = (gt == 0) ? &g_f0[r * D + cg]
                                   : &g_Ap[((size_t)r * T + gt - 1) * D + cg];
                else if constexpr (MODE == 1)
                    p_ = (gt == 0) ? &g_z[r * H + cg]
                                   : &g_Z1[((size_t)r * T + gt - 1) * H + cg];
                else if constexpr (MODE == 2)
                    p_ = (gt == 0) ? &g_base[r * D + cg]
                                   : &g_F2[((size_t)r * T + gt - 1) * D + cg];
                else if constexpr (MODE == 3)
                    p_ = &g_dzp[r * H + cg];
                else
                    p_ = &dst[r * D + cg];
                red4(p_, f);
            }
        }
    }
}

// ---------------- K5: metanet -------------------------------------------------
__global__ void meta_kernel(const float* __restrict__ mW1, const float* __restrict__ mb1,
                            const float* __restrict__ mW2, const float* __restrict__ mb2)
{
    __shared__ float sb[D];
    __shared__ float sg[MH];
    const int b = blockIdx.x;
    const int tid = threadIdx.x;   // 192
    for (int i = tid; i < D; i += MH) sb[i] = g_base[b * D + i];
    __syncthreads();
    float h = mb1[tid];
    #pragma unroll 8
    for (int k = 0; k < D; k++) h = fmaf(sb[k], mW1[k * MH + tid], h);
    sg[tid] = fmaxf(h, 0.f);
    __syncthreads();
    if (tid < T * 6) {
        float cc = mb2[tid];
        #pragma unroll 8
        for (int k = 0; k < MH; k++) cc = fmaf(sg[k], mW2[k * (T * 6) + tid], cc);
        g_coef[b * (T * 6) + tid] = cc;
    }
}

// ---------------- K6: coefficient contraction + output init ------------------
__global__ void combine_kernel(const float* __restrict__ dbp,
                               const float* __restrict__ db1,
                               const float* __restrict__ db2,
                               float* __restrict__ dst)
{
    __shared__ float sc[T * 6];
    const int b = blockIdx.x;
    const int tid = threadIdx.x;
    if (tid < T * 6) sc[tid] = g_coef[b * (T * 6) + tid];
    __syncthreads();
    const int n = blockIdx.y * 256 + tid;
    if (n < D) {
        float s = 0.f;
        #pragma unroll
        for (int t = 0; t < T; t++)
            s += sc[t * 6 + 0] * g_Ap[((size_t)b * T + t) * D + n]
               + sc[t * 6 + 1] * dbp[t * D + n];
        g_df0[b * D + n] = s;
    } else if (n < D + H) {
        const int j = n - D;
        float s = 0.f;
        #pragma unroll
        for (int t = 0; t < T; t++)
            s += sc[t * 6 + 2] * g_Z1[((size_t)b * T + t) * H + j]
               + sc[t * 6 + 3] * db1[t * H + j];
        g_dzp[b * H + j] = s;
    } else {
        const int j = n - D - H;
        float s = g_base[b * D + j];
        #pragma unroll
        for (int t = 0; t < T; t++)
            s += sc[t * 6 + 4] * g_F2[((size_t)b * T + t) * D + j]
               + sc[t * 6 + 5] * db2[t * D + j];
        dst[b * D + j] = s;
    }
}

// ---------------- launch ------------------------------------------------------
extern "C" void kernel_launch(void* const* d_in, const int* in_sizes, int n_in,
                              void* d_out, int out_size)
{
    const float* x   = (const float*)d_in[0];
    const float* Wp  = (const float*)d_in[1];
    const float* bp  = (const float*)d_in[2];
    const float* W1  = (const float*)d_in[3];
    const float* b1  = (const float*)d_in[4];
    const float* W2  = (const float*)d_in[5];
    const float* b2  = (const float*)d_in[6];
    const float* dWp = (const float*)d_in[7];
    const float* dbp = (const float*)d_in[8];
    const float* dW1 = (const float*)d_in[9];
    const float* db1 = (const float*)d_in[10];
    const float* dW2 = (const float*)d_in[11];
    const float* db2 = (const float*)d_in[12];
    const float* mW1 = (const float*)d_in[13];
    const float* mb1 = (const float*)d_in[14];
    const float* mW2 = (const float*)d_in[15];
    const float* mb2 = (const float*)d_in[16];
    float* out = (float*)d_out;

    patch_mean_kernel<<<96, 256>>>(x);
    init_kernel<<<384, 256>>>(bp, b1, b2);
    // K2: f0/Ap   nblk=27, Y=16 (KC=48,  6 tiles)  432 blocks
    gemm8<768, 768, 0><<<dim3(27, 16), 256>>>(Wp, dWp, nullptr);
    // K3: z/Z1    nblk=108, Y=8 (KC=96, 12 tiles)  864 blocks
    gemm8<768, 3072, 1><<<dim3(108, 8), 256>>>(W1, dW1, nullptr);
    relu_kernel<<<384, 256>>>();
    // K4: base/F2 nblk=27, Y=32 (KC=96, 12 tiles)  864 blocks
    gemm8<3072, 768, 2><<<dim3(27, 32), 256>>>(W2, dW2, nullptr);
    meta_kernel<<<B, MH>>>(mW1, mb1, mW2, mb2);
    combine_kernel<<<dim3(B, 18), 256>>>(dbp, db1, db2, out);
    // K7: dzp += df0@W1  nblk=12, Y=24 (KC=32, 4 tiles) 288 blocks
    gemm8<768, 3072, 3><<<dim3(12, 24), 256>>>(W1, nullptr, nullptr);
    mask_kernel<<<384, 256>>>();
    // K8: out += df@W2   nblk=3, Y=96 (KC=32, 4 tiles) 288 blocks
    gemm8<3072, 768, 4><<<dim3(3, 96), 256>>>(W2, nullptr, out);
}

// round 15
// speedup vs baseline: 1.0106x; 1.0106x over previous
#include <cuda_runtime.h>
#include <cstdint>

#define B  32
#define D  768
#define H  3072
#define T  8
#define MH 192

typedef unsigned long long ull;

// ---------------- scratch (device globals) ----------------------------------
__device__ float g_m  [B*D];
__device__ float g_f0 [B*D];
__device__ float g_Ap [B*T*D];
__device__ float g_z  [B*H];
__device__ float g_f  [B*H];
__device__ float g_Z1 [B*T*H];
__device__ float g_base[B*D];
__device__ float g_F2 [B*T*D];
__device__ float g_coef[B*T*6];
__device__ float g_df0[B*D];
__device__ float g_dzp[B*H];
__device__ float g_df [B*H];

// ---------------- packed f32x2 helpers --------------------------------------
__device__ __forceinline__ void ffma2(ull &d, ull a, ull b) {
    asm("fma.rn.f32x2 %0, %1, %2, %0;" : "+l"(d) : "l"(a), "l"(b));
}
__device__ __forceinline__ ull bcast2(float w) {
    ull r; asm("mov.b64 %0, {%1, %1};" : "=l"(r) : "f"(w)); return r;
}
__device__ __forceinline__ void unpack2(ull v, float &lo, float &hi) {
    asm("mov.b64 {%0, %1}, %2;" : "=f"(lo), "=f"(hi) : "l"(v));
}
__device__ __forceinline__ ull addp(ull a, ull b) {
    ull r; asm("add.rn.f32x2 %0, %1, %2;" : "=l"(r) : "l"(a), "l"(b)); return r;
}
__device__ __forceinline__ void red4(float* p, float4 f) {
    asm volatile("red.global.add.v4.f32 [%0], {%1,%2,%3,%4};"
                 :: "l"(p), "f"(f.x), "f"(f.y), "f"(f.z), "f"(f.w) : "memory");
}
// ---------------- mbarrier helpers -------------------------------------------
__device__ __forceinline__ void mbar_init(unsigned mbar, unsigned cnt) {
    asm volatile("mbarrier.init.shared.b64 [%0], %1;" :: "r"(mbar), "r"(cnt) : "memory");
}
__device__ __forceinline__ void mbar_wait(unsigned mbar, unsigned parity) {
    asm volatile(
        "{\n\t.reg .pred P;\n"
        "W_%=:\n\t"
        "mbarrier.try_wait.parity.acquire.cta.shared::cta.b64 P, [%0], %1;\n\t"
        "@P bra D_%=;\n\t"
        "bra W_%=;\n"
        "D_%=:\n\t}"
        :: "r"(mbar), "r"(parity) : "memory");
}
__device__ __forceinline__ void mbar_arrive(unsigned mbar) {
    asm volatile("mbarrier.arrive.release.cta.shared::cta.b64 _, [%0];"
                 :: "r"(mbar) : "memory");
}
template<int NC>
__device__ __forceinline__ void issue_tile(const float* wrow0, int t,
                                           unsigned swb, unsigned fullb) {
    asm volatile("mbarrier.arrive.expect_tx.shared.b64 _, [%0], %1;"
                 :: "r"(fullb), "r"(8192u) : "memory");
    const float* src = wrow0 + (size_t)t * 8 * NC;
    unsigned dst = swb + (unsigned)(t % 5) * 8192u;
    #pragma unroll
    for (int r = 0; r < 8; r++) {
        asm volatile(
            "cp.async.bulk.shared::cta.global.mbarrier::complete_tx::bytes "
            "[%0], [%1], 1024, [%2];"
            :: "r"(dst + r * 1024u), "l"(src + (size_t)r * NC), "r"(fullb)
            : "memory");
    }
}

// ---------------- K1: patch mean ---------------------------------------------
__global__ void patch_mean_kernel(const float* __restrict__ x) {
    int bc = blockIdx.x;            // 0..95
    int b = bc / 3, c = bc % 3;
    int tid = threadIdx.x;          // 256
    int dy = tid >> 4, dx = tid & 15;
    const float* base = x + (((size_t)b * 3 + c) * 224 + dy) * 224 + dx;
    float s = 0.f;
    #pragma unroll
    for (int py = 0; py < 14; py++) {
        const float* r = base + py * 16 * 224;
        #pragma unroll
        for (int px = 0; px < 14; px++) s += r[px * 16];
    }
    g_m[b * D + c * 256 + dy * 16 + dx] = s * (1.0f / 196.0f);
}

// ---------------- init: bias preload + zeros ---------------------------------
__global__ void init_kernel(const float* __restrict__ bp,
                            const float* __restrict__ b1,
                            const float* __restrict__ b2) {
    int i = blockIdx.x * 256 + threadIdx.x;
    if (i < B * D) { g_f0[i] = bp[i % D]; g_base[i] = b2[i % D]; }
    if (i < B * H) g_z[i] = b1[i % H];
    for (int j = i; j < B * T * D; j += gridDim.x * 256) { g_Ap[j] = 0.f; g_F2[j] = 0.f; }
    for (int j = i; j < B * T * H; j += gridDim.x * 256) g_Z1[j] = 0.f;
}

__global__ void relu_kernel() {
    int i = blockIdx.x * 256 + threadIdx.x;
    if (i < B * H) g_f[i] = fmaxf(g_z[i], 0.f);
}
__global__ void mask_kernel() {
    int i = blockIdx.x * 256 + threadIdx.x;
    if (i < B * H) g_df[i] = (g_z[i] > 0.f) ? g_dzp[i] : 0.f;
}

// ---------------- skinny GEMM v8: free-running warp pipeline ------------------
// Tile 256 cols x 32 rows; warps = 2ct x 2rh x 2kh; lane = 4 cols x 8 row-pairs
// packed over rows. NO __syncthreads in main loop: W via 5-stage bulk-DMA with
// full/empty mbarriers (warps drift up to 4 tiles); A warp-private smem.
// MODE: 0:g_f0/g_Ap  1:g_z/g_Z1  2:g_base/g_F2  3:g_dzp(A=g_df0)  4:dst(A=g_df)
template<int KTOT, int NC, int MODE>
__global__ void __launch_bounds__(256, 2) gemm8(
    const float* __restrict__ W0,
    const float* __restrict__ Wd,
    float* __restrict__ dst)
{
    __shared__ __align__(128) float sW[5 * 2048];   // 40KB: 5 stages of 8k x 256
    __shared__ __align__(16)  float sA[8 * 128];    // 4KB: per-warp 8k x 16
    __shared__ __align__(8)   ull   smb[10];        // full[5], empty[5]

    const int tid  = threadIdx.x;
    const int w    = tid >> 5;
    const int lane = tid & 31;
    const int ct   = w & 1;
    const int rh   = (w >> 1) & 1;
    const int kh   = w >> 2;

    const unsigned swb  = (unsigned)__cvta_generic_to_shared(sW);
    const unsigned mbf  = (unsigned)__cvta_generic_to_shared(smb);      // full
    const unsigned mbe  = mbf + 40;                                     // empty

    const float* A;
    if      (MODE == 0) A = g_m;
    else if (MODE == 1) A = g_f0;
    else if (MODE == 2) A = g_f;
    else if (MODE == 3) A = g_df0;
    else                A = g_df;

    const int n0 = blockIdx.x * 256;
    const int gt = n0 / NC;
    const int c0 = n0 % NC;
    const float* wbase = (gt == 0 ? W0 : Wd + (size_t)(gt - 1) * KTOT * NC) + c0;

    const int KC    = KTOT / gridDim.y;
    const int kbeg  = blockIdx.y * KC;
    const int tiles = KC >> 3;
    const float* wrow0 = wbase + (size_t)kbeg * NC;

    if (tid == 0) {
        #pragma unroll
        for (int i = 0; i < 5; i++) { mbar_init(mbf + i * 8, 1); mbar_init(mbe + i * 8, 8); }
        asm volatile("fence.proxy.async.shared::cta;" ::: "memory");
    }
    __syncthreads();

    if (tid == 0) {
        #pragma unroll
        for (int tp = 0; tp < 4; tp++)
            if (tp < tiles) issue_tile<NC>(wrow0, tp, swb, mbf + (tp % 5) * 8);
    }

    ull acc[32];
    #pragma unroll
    for (int i = 0; i < 32; i++) acc[i] = 0ULL;

    // per-warp A: rows rh*16+(lane&15), k quad (lane>>4)*4
    const int r16 = lane & 15, kq = (lane >> 4) * 4;
    const float* aptr = A + (size_t)(rh * 16 + r16) * KTOT + kbeg + kq;
    float* sAw = sA + w * 128;
    float4 av = *(const float4*)aptr;

    for (int t = 0; t < tiles; t++) {
        float4 avn;
        if (t + 1 < tiles) avn = *(const float4*)(aptr + (t + 1) * 8);
        __syncwarp();
        sAw[(kq + 0) * 16 + r16] = av.x;
        sAw[(kq + 1) * 16 + r16] = av.y;
        sAw[(kq + 2) * 16 + r16] = av.z;
        sAw[(kq + 3) * 16 + r16] = av.w;
        __syncwarp();

        mbar_wait(mbf + (t % 5) * 8, (unsigned)((t / 5) & 1));

        const float* sWk = &sW[(t % 5) * 2048 + ct * 128 + 4 * lane];
        #pragma unroll
        for (int kk = 0; kk < 4; kk++) {
            const int k = 2 * kk + kh;
            float4 wv = *(const float4*)(sWk + k * 256);
            const ulonglong2* ap = (const ulonglong2*)(sAw + k * 16);
            ulonglong2 a0 = ap[0], a1 = ap[1], a2 = ap[2], a3 = ap[3];
            ull wb0 = bcast2(wv.x), wb1 = bcast2(wv.y);
            ull wb2 = bcast2(wv.z), wb3 = bcast2(wv.w);
            ffma2(acc[0],  a0.x, wb0); ffma2(acc[1],  a0.x, wb1);
            ffma2(acc[2],  a0.x, wb2); ffma2(acc[3],  a0.x, wb3);
            ffma2(acc[4],  a0.y, wb0); ffma2(acc[5],  a0.y, wb1);
            ffma2(acc[6],  a0.y, wb2); ffma2(acc[7],  a0.y, wb3);
            ffma2(acc[8],  a1.x, wb0); ffma2(acc[9],  a1.x, wb1);
            ffma2(acc[10], a1.x, wb2); ffma2(acc[11], a1.x, wb3);
            ffma2(acc[12], a1.y, wb0); ffma2(acc[13], a1.y, wb1);
            ffma2(acc[14], a1.y, wb2); ffma2(acc[15], a1.y, wb3);
            ffma2(acc[16], a2.x, wb0); ffma2(acc[17], a2.x, wb1);
            ffma2(acc[18], a2.x, wb2); ffma2(acc[19], a2.x, wb3);
            ffma2(acc[20], a2.y, wb0); ffma2(acc[21], a2.y, wb1);
            ffma2(acc[22], a2.y, wb2); ffma2(acc[23], a2.y, wb3);
            ffma2(acc[24], a3.x, wb0); ffma2(acc[25], a3.x, wb1);
            ffma2(acc[26], a3.x, wb2); ffma2(acc[27], a3.x, wb3);
            ffma2(acc[28], a3.y, wb0); ffma2(acc[29], a3.y, wb1);
            ffma2(acc[30], a3.y, wb2); ffma2(acc[31], a3.y, wb3);
        }

        if (lane == 0) mbar_arrive(mbe + (t % 5) * 8);

        if (tid == 0 && t + 4 < tiles) {
            const int tp = t + 4;
            mbar_wait(mbe + (tp % 5) * 8, (unsigned)(((tp / 5) & 1) ^ 1));
            issue_tile<NC>(wrow0, tp, swb, mbf + (tp % 5) * 8);
        }
        av = avn;
    }

    // ---- merge kh pair via one smem round, flush once ----
    __syncthreads();
    ull* sred = (ull*)sW;
    const int role = w & 3;               // (ct, rh)
    if (kh == 1) {
        #pragma unroll
        for (int i = 0; i < 32; i++) sred[role * 1024 + i * 32 + lane] = acc[i];
    }
    __syncthreads();
    if (kh == 0) {
        #pragma unroll
        for (int i = 0; i < 32; i++)
            acc[i] = addp(acc[i], sred[role * 1024 + i * 32 + lane]);

        const int cg = c0 + ct * 128 + 4 * lane;
        #pragma unroll
        for (int p = 0; p < 8; p++) {
            const int row = rh * 16 + 2 * p;
            float4 vlo, vhi;
            unpack2(acc[p * 4 + 0], vlo.x, vhi.x);
            unpack2(acc[p * 4 + 1], vlo.y, vhi.y);
            unpack2(acc[p * 4 + 2], vlo.z, vhi.z);
            unpack2(acc[p * 4 + 3], vlo.w, vhi.w);
            #pragma unroll
            for (int h = 0; h < 2; h++) {
                const int r = row + h;
                float4 f = h ? vhi : vlo;
                float* p_;
                if constexpr (MODE == 0)
                    p_ = (gt == 0) ? &g_f0[r * D + cg]
                                   : &g_Ap[((size_t)r * T + gt - 1) * D + cg];
                else if constexpr (MODE == 1)
                    p_ = (gt == 0) ? &g_z[r * H + cg]
                                   : &g_Z1[((size_t)r * T + gt - 1) * H + cg];
                else if constexpr (MODE == 2)
                    p_ = (gt == 0) ? &g_base[r * D + cg]
                                   : &g_F2[((size_t)r * T + gt - 1) * D + cg];
                else if constexpr (MODE == 3)
                    p_ = &g_dzp[r * H + cg];
                else
                    p_ = &dst[r * D + cg];
                red4(p_, f);
            }
        }
    }
}

// ---------------- K5: metanet -------------------------------------------------
__global__ void meta_kernel(const float* __restrict__ mW1, const float* __restrict__ mb1,
                            const float* __restrict__ mW2, const float* __restrict__ mb2)
{
    __shared__ float sb[D];
    __shared__ float sg[MH];
    const int b = blockIdx.x;
    const int tid = threadIdx.x;   // 192
    for (int i = tid; i < D; i += MH) sb[i] = g_base[b * D + i];
    __syncthreads();
    float h = mb1[tid];
    #pragma unroll 8
    for (int k = 0; k < D; k++) h = fmaf(sb[k], mW1[k * MH + tid], h);
    sg[tid] = fmaxf(h, 0.f);
    __syncthreads();
    if (tid < T * 6) {
        float cc = mb2[tid];
        #pragma unroll 8
        for (int k = 0; k < MH; k++) cc = fmaf(sg[k], mW2[k * (T * 6) + tid], cc);
        g_coef[b * (T * 6) + tid] = cc;
    }
}

// ---------------- K6: coefficient contraction + output init ------------------
__global__ void combine_kernel(const float* __restrict__ dbp,
                               const float* __restrict__ db1,
                               const float* __restrict__ db2,
                               float* __restrict__ dst)
{
    __shared__ float sc[T * 6];
    const int b = blockIdx.x;
    const int tid = threadIdx.x;
    if (tid < T * 6) sc[tid] = g_coef[b * (T * 6) + tid];
    __syncthreads();
    const int n = blockIdx.y * 256 + tid;
    if (n < D) {
        float s = 0.f;
        #pragma unroll
        for (int t = 0; t < T; t++)
            s += sc[t * 6 + 0] * g_Ap[((size_t)b * T + t) * D + n]
               + sc[t * 6 + 1] * dbp[t * D + n];
        g_df0[b * D + n] = s;
    } else if (n < D + H) {
        const int j = n - D;
        float s = 0.f;
        #pragma unroll
        for (int t = 0; t < T; t++)
            s += sc[t * 6 + 2] * g_Z1[((size_t)b * T + t) * H + j]
               + sc[t * 6 + 3] * db1[t * H + j];
        g_dzp[b * H + j] = s;
    } else {
        const int j = n - D - H;
        float s = g_base[b * D + j];
        #pragma unroll
        for (int t = 0; t < T; t++)
            s += sc[t * 6 + 4] * g_F2[((size_t)b * T + t) * D + j]
               + sc[t * 6 + 5] * db2[t * D + j];
        dst[b * D + j] = s;
    }
}

// ---------------- launch ------------------------------------------------------
extern "C" void kernel_launch(void* const* d_in, const int* in_sizes, int n_in,
                              void* d_out, int out_size)
{
    const float* x   = (const float*)d_in[0];
    const float* Wp  = (const float*)d_in[1];
    const float* bp  = (const float*)d_in[2];
    const float* W1  = (const float*)d_in[3];
    const float* b1  = (const float*)d_in[4];
    const float* W2  = (const float*)d_in[5];
    const float* b2  = (const float*)d_in[6];
    const float* dWp = (const float*)d_in[7];
    const float* dbp = (const float*)d_in[8];
    const float* dW1 = (const float*)d_in[9];
    const float* db1 = (const float*)d_in[10];
    const float* dW2 = (const float*)d_in[11];
    const float* db2 = (const float*)d_in[12];
    const float* mW1 = (const float*)d_in[13];
    const float* mb1 = (const float*)d_in[14];
    const float* mW2 = (const float*)d_in[15];
    const float* mb2 = (const float*)d_in[16];
    float* out = (float*)d_out;

    patch_mean_kernel<<<96, 256>>>(x);
    init_kernel<<<384, 256>>>(bp, b1, b2);
    // K2: f0/Ap   nblk=27, Y=16 (KC=48,  6 tiles)  432 blocks
    gemm8<768, 768, 0><<<dim3(27, 16), 256>>>(Wp, dWp, nullptr);
    // K3: z/Z1    nblk=108, Y=8 (KC=96, 12 tiles)  864 blocks
    gemm8<768, 3072, 1><<<dim3(108, 8), 256>>>(W1, dW1, nullptr);
    relu_kernel<<<384, 256>>>();
    // K4: base/F2 nblk=27, Y=32 (KC=96, 12 tiles)  864 blocks
    gemm8<3072, 768, 2><<<dim3(27, 32), 256>>>(W2, dW2, nullptr);
    meta_kernel<<<B, MH>>>(mW1, mb1, mW2, mb2);
    combine_kernel<<<dim3(B, 18), 256>>>(dbp, db1, db2, out);
    // K7: dzp += df0@W1  nblk=12, Y=24 (KC=32, 4 tiles) 288 blocks
    gemm8<768, 3072, 3><<<dim3(12, 24), 256>>>(W1, nullptr, nullptr);
    mask_kernel<<<384, 256>>>();
    // K8: out += df@W2   nblk=3, Y=96 (KC=32, 4 tiles) 288 blocks
    gemm8<3072, 768, 4><<<dim3(3, 96), 256>>>(W2, nullptr, out);
}